// round 1
// baseline (speedup 1.0000x reference)
#include <cuda_runtime.h>

#define D   256
#define D4  64
#define K   8192
#define BT  32768
#define BM  64
#define BN  64
#define NTHREADS 256

__device__ double g_sse;
__device__ float  g_cbnorm[K];

__global__ void vq_zero() { g_sse = 0.0; }

// codebook row norms: one warp per code
__global__ void vq_norms(const float* __restrict__ cb) {
    int warp = (blockIdx.x * blockDim.x + threadIdx.x) >> 5;
    int lane = threadIdx.x & 31;
    if (warp >= K) return;
    const float* row = cb + (size_t)warp * D;
    float s = 0.f;
    for (int d = lane; d < D; d += 32) { float v = row[d]; s = __fmaf_rn(v, v, s); }
    #pragma unroll
    for (int o = 16; o; o >>= 1) s += __shfl_xor_sync(0xffffffffu, s, o);
    if (lane == 0) g_cbnorm[warp] = s;
}

__global__ __launch_bounds__(NTHREADS, 1) void vq_main(
    const float* __restrict__ x, const float* __restrict__ cb,
    float* __restrict__ outq, float* __restrict__ outidx)
{
    extern __shared__ float smem[];
    float4* xs   = (float4*)smem;                 // [BM][D4+1]
    float4* bs   = xs + BM * (D4 + 1);            // [BN][9]
    float*  rowa = (float*)(bs + BN * 9);         // [BM]
    float*  redv = rowa + BM;                     // [BM][16]
    int*    redi = (int*)(redv + BM * 16);        // [BM][16]
    int*    sel  = redi + BM * 16;                // [BM]

    const int tid = threadIdx.x;
    const int tx = tid & 15, ty = tid >> 4;
    const int row0 = blockIdx.x * BM;
    const float4* xg = (const float4*)x;
    const float4* cg = (const float4*)cb;

    // load x tile (64 x 256 f32) into shared
    for (int i = tid; i < BM * D4; i += NTHREADS) {
        int r = i >> 6, c = i & 63;
        xs[r * (D4 + 1) + c] = xg[(size_t)(row0 + r) * D4 + c];
    }
    __syncthreads();

    // per-row ||x||^2 in fp32, sequential over d (mirrors reference fp32 sum)
    if (tid < BM) {
        float s = 0.f;
        const float4* xr = xs + tid * (D4 + 1);
        for (int c = 0; c < D4; ++c) {
            float4 v = xr[c];
            s = __fmaf_rn(v.x, v.x, s);
            s = __fmaf_rn(v.y, v.y, s);
            s = __fmaf_rn(v.z, v.z, s);
            s = __fmaf_rn(v.w, v.w, s);
        }
        rowa[tid] = s;
    }

    float bestv[4]; int besti[4];
    #pragma unroll
    for (int i = 0; i < 4; i++) { bestv[i] = 3.4e38f; besti[i] = 0; }

    for (int ct = 0; ct < K / BN; ++ct) {
        const int cbase = ct * BN;
        float acc[4][4];
        #pragma unroll
        for (int i = 0; i < 4; i++)
            #pragma unroll
            for (int j = 0; j < 4; j++) acc[i][j] = 0.f;

        for (int dc = 0; dc < 8; ++dc) {          // 8 chunks of 32 floats over D
            __syncthreads();
            for (int i = tid; i < BN * 8; i += NTHREADS) {
                int r = i >> 3, c = i & 7;
                bs[r * 9 + c] = cg[(size_t)(cbase + r) * D4 + dc * 8 + c];
            }
            __syncthreads();
            #pragma unroll
            for (int k8 = 0; k8 < 8; ++k8) {
                float4 av[4], bv[4];
                #pragma unroll
                for (int i = 0; i < 4; i++) av[i] = xs[(ty * 4 + i) * (D4 + 1) + dc * 8 + k8];
                #pragma unroll
                for (int j = 0; j < 4; j++) bv[j] = bs[(tx * 4 + j) * 9 + k8];
                #pragma unroll
                for (int i = 0; i < 4; i++)
                    #pragma unroll
                    for (int j = 0; j < 4; j++) {
                        acc[i][j] = __fmaf_rn(av[i].x, bv[j].x, acc[i][j]);
                        acc[i][j] = __fmaf_rn(av[i].y, bv[j].y, acc[i][j]);
                        acc[i][j] = __fmaf_rn(av[i].z, bv[j].z, acc[i][j]);
                        acc[i][j] = __fmaf_rn(av[i].w, bv[j].w, acc[i][j]);
                    }
            }
        }

        // distance + running argmin (replicate reference rounding exactly)
        #pragma unroll
        for (int j = 0; j < 4; j++) {
            int code = cbase + tx * 4 + j;
            float bn = g_cbnorm[code];
            #pragma unroll
            for (int i = 0; i < 4; i++) {
                float t = __fadd_rn(rowa[ty * 4 + i], bn);
                float dist = __fsub_rn(t, __fmul_rn(2.0f, acc[i][j]));
                if (dist < bestv[i]) { bestv[i] = dist; besti[i] = code; }  // in-order: strict < keeps lowest idx
            }
        }
    }

    // cross-thread argmin reduction per row with lowest-index tie-break
    #pragma unroll
    for (int i = 0; i < 4; i++) {
        redv[(ty * 4 + i) * 16 + tx] = bestv[i];
        redi[(ty * 4 + i) * 16 + tx] = besti[i];
    }
    __syncthreads();
    if (tid < BM) {
        float bv = redv[tid * 16]; int bi = redi[tid * 16];
        for (int t = 1; t < 16; ++t) {
            float v = redv[tid * 16 + t]; int ii = redi[tid * 16 + t];
            if (v < bv || (v == bv && ii < bi)) { bv = v; bi = ii; }
        }
        sel[tid] = bi;
        if (outidx) outidx[row0 + tid] = (float)bi;
    }
    __syncthreads();

    // gather quantized rows, write, accumulate SSE
    float sse = 0.f;
    float4* oq = (float4*)outq;
    for (int i = tid; i < BM * D4; i += NTHREADS) {
        int r = i >> 6, c = i & 63;
        float4 q = cg[(size_t)sel[r] * D4 + c];
        oq[(size_t)(row0 + r) * D4 + c] = q;
        float4 xv = xs[r * (D4 + 1) + c];
        float dx = q.x - xv.x, dy = q.y - xv.y, dz = q.z - xv.z, dw = q.w - xv.w;
        sse += dx * dx + dy * dy + dz * dz + dw * dw;
    }
    #pragma unroll
    for (int o = 16; o; o >>= 1) sse += __shfl_xor_sync(0xffffffffu, sse, o);
    if ((tid & 31) == 0) atomicAdd(&g_sse, (double)sse);
}

__global__ void vq_fin(float* outloss) {
    // e_latent_loss == q_latent_loss in value; loss = 1.25 * MSE
    *outloss = (float)((g_sse / 8388608.0) * 1.25);
}

extern "C" void kernel_launch(void* const* d_in, const int* in_sizes, int n_in,
                              void* d_out, int out_size) {
    const float* x  = (const float*)d_in[0];
    const float* cb = (const float*)d_in[1];
    // defensive: identify by element count (8388608 vs 2097152)
    if (n_in >= 2 && in_sizes[0] == K * D && in_sizes[1] == BT * D) {
        const float* t = x; x = cb; cb = t;
    }

    const size_t NQ = (size_t)BT * D;             // 8388608
    float* outq    = (float*)d_out;
    float* outidx  = nullptr;
    float* outloss = nullptr;
    if ((size_t)out_size >= NQ + BT) outidx = outq + NQ;
    if ((size_t)out_size >= NQ + BT + 1) outloss = outq + NQ + BT;
    else if ((size_t)out_size == NQ + 1) outloss = outq + NQ;

    // shared: xs 64*65*4 f32 + bs 64*9*4 + rowa 64 + redv 1024 + redi 1024 + sel 64
    size_t shmem = (size_t)(BM * (D4 + 1) * 4 + BN * 9 * 4 + BM + BM * 16 + BM * 16 + BM) * sizeof(float);
    cudaFuncSetAttribute(vq_main, cudaFuncAttributeMaxDynamicSharedMemorySize, (int)(shmem + 1024));

    vq_zero<<<1, 1>>>();
    vq_norms<<<K / 8, 256>>>(cb);
    vq_main<<<BT / BM, NTHREADS, shmem>>>(x, cb, outq, outidx);
    if (outloss) vq_fin<<<1, 1>>>(outloss);
}

// round 2
// speedup vs baseline: 6.2050x; 6.2050x over previous
#include <cuda_runtime.h>
#include <cuda_bf16.h>
#include <cstdint>

#define D   256
#define K   8192
#define BT  32768
#define BM  128
#define BN  128
#define NTHREADS 256
#define AST 264   // resident A smem stride (bf16 elems): 256 + 8 pad -> conflict-free frag loads
#define BST 40    // B tile smem stride (bf16 elems): 32 + 8 pad -> conflict-free frag loads

__device__ double g_sse;
__device__ float  g_cbnorm[K];
__device__ __nv_bfloat16 g_xh[(size_t)BT * D];
__device__ __nv_bfloat16 g_xl[(size_t)BT * D];
__device__ __nv_bfloat16 g_ch[(size_t)K * D];
__device__ __nv_bfloat16 g_cl[(size_t)K * D];

__global__ void vq_zero() { g_sse = 0.0; }

// codebook row norms in fp32: one warp per code
__global__ void vq_norms(const float* __restrict__ cb) {
    int warp = (blockIdx.x * blockDim.x + threadIdx.x) >> 5;
    int lane = threadIdx.x & 31;
    if (warp >= K) return;
    const float* row = cb + (size_t)warp * D;
    float s = 0.f;
    for (int d = lane; d < D; d += 32) { float v = row[d]; s = __fmaf_rn(v, v, s); }
    #pragma unroll
    for (int o = 16; o; o >>= 1) s += __shfl_xor_sync(0xffffffffu, s, o);
    if (lane == 0) g_cbnorm[warp] = s;
}

// fp32 -> bf16 hi/lo split
__global__ void vq_split(const float* __restrict__ src, __nv_bfloat16* __restrict__ hi,
                         __nv_bfloat16* __restrict__ lo, int n) {
    int i = blockIdx.x * blockDim.x + threadIdx.x;
    if (i < n) {
        float v = src[i];
        __nv_bfloat16 h = __float2bfloat16_rn(v);
        hi[i] = h;
        lo[i] = __float2bfloat16_rn(v - __bfloat162float(h));
    }
}

#define MMA16816(c, a0, a1, a2, a3, b0, b1)                                  \
    asm volatile(                                                            \
        "mma.sync.aligned.m16n8k16.row.col.f32.bf16.bf16.f32 "               \
        "{%0,%1,%2,%3}, {%4,%5,%6,%7}, {%8,%9}, {%0,%1,%2,%3};"              \
        : "+f"((c)[0]), "+f"((c)[1]), "+f"((c)[2]), "+f"((c)[3])             \
        : "r"(a0), "r"(a1), "r"(a2), "r"(a3), "r"(b0), "r"(b1))

__global__ __launch_bounds__(NTHREADS, 1) void vq_main(
    const float* __restrict__ x, const float* __restrict__ cb,
    float* __restrict__ outq, float* __restrict__ outidx)
{
    extern __shared__ char smem_raw[];
    __nv_bfloat16* xh_s = (__nv_bfloat16*)smem_raw;        // [BM][AST]
    __nv_bfloat16* xl_s = xh_s + BM * AST;                 // [BM][AST]
    __nv_bfloat16* bs   = xl_s + BM * AST;                 // [2][BN][BST]
    float* cbs  = (float*)(bs + 2 * BN * BST);             // [BN]
    float* rowa = cbs + BN;                                // [BM]
    float* redv = rowa + BM;                               // [BM*16]
    int*   redi = (int*)(redv + BM * 16);                  // [BM*16]
    int*   sel  = redi + BM * 16;                          // [BM]

    const int tid  = threadIdx.x;
    const int lane = tid & 31;
    const int wid  = tid >> 5;
    const int wm   = (wid >> 2) * 64;   // warp row offset (2 warp-rows)
    const int wn   = (wid & 3) * 32;    // warp col offset (4 warp-cols)
    const int row0 = blockIdx.x * BM;
    const int lr   = lane >> 2;         // 0..7
    const int lc2  = (lane & 3) * 2;    // 0,2,4,6

    // ---- load resident A (xh, xl) into shared ----
    for (int i = tid; i < BM * 32; i += NTHREADS) {
        int r = i >> 5, c = i & 31;   // c: chunk of 8 bf16
        *(float4*)&xh_s[r * AST + c * 8] = *(const float4*)&g_xh[(size_t)(row0 + r) * D + c * 8];
        *(float4*)&xl_s[r * AST + c * 8] = *(const float4*)&g_xl[(size_t)(row0 + r) * D + c * 8];
    }
    // ---- per-row ||x||^2, sequential fp32 (matches R1-passing behavior) ----
    if (tid < BM) {
        float s = 0.f;
        const float* xr = x + (size_t)(row0 + tid) * D;
        for (int d = 0; d < D; ++d) s = __fmaf_rn(xr[d], xr[d], s);
        rowa[tid] = s;
    }
    __syncthreads();

    float bestv[8]; int besti[8];
    #pragma unroll
    for (int i = 0; i < 8; i++) { bestv[i] = 3.4e38f; besti[i] = 0; }

    for (int ct = 0; ct < K / BN; ++ct) {
        const int cbase = ct * BN;
        __syncthreads();                      // cbs reuse guard
        if (tid < BN) cbs[tid] = g_cbnorm[cbase + tid];

        float acc[4][4][4];
        #pragma unroll
        for (int mf = 0; mf < 4; mf++)
            #pragma unroll
            for (int nf = 0; nf < 4; nf++)
                #pragma unroll
                for (int q = 0; q < 4; q++) acc[mf][nf][q] = 0.f;

        // ---- stage tile 0 ----
        {
            #pragma unroll
            for (int h = 0; h < 2; ++h) {
                int chunk = tid + h * NTHREADS;
                int rr = chunk >> 2, kc = chunk & 3;
                const __nv_bfloat16* gp = g_ch + (size_t)(cbase + rr) * D + kc * 8;
                uint32_t sp = (uint32_t)__cvta_generic_to_shared(&bs[rr * BST + kc * 8]);
                asm volatile("cp.async.cg.shared.global [%0], [%1], 16;" :: "r"(sp), "l"(gp));
            }
            asm volatile("cp.async.commit_group;");
        }

        for (int t = 0; t < 16; ++t) {
            if (t < 15) {
                int tn = t + 1;
                const __nv_bfloat16* src = (tn < 8) ? g_ch : g_cl;
                int kt = (tn < 8) ? tn : tn - 8;
                #pragma unroll
                for (int h = 0; h < 2; ++h) {
                    int chunk = tid + h * NTHREADS;
                    int rr = chunk >> 2, kc = chunk & 3;
                    const __nv_bfloat16* gp = src + (size_t)(cbase + rr) * D + kt * 32 + kc * 8;
                    uint32_t sp = (uint32_t)__cvta_generic_to_shared(
                        &bs[(tn & 1) * BN * BST + rr * BST + kc * 8]);
                    asm volatile("cp.async.cg.shared.global [%0], [%1], 16;" :: "r"(sp), "l"(gp));
                }
                asm volatile("cp.async.commit_group;");
                asm volatile("cp.async.wait_group 1;");
            } else {
                asm volatile("cp.async.wait_group 0;");
            }
            __syncthreads();

            const __nv_bfloat16* bt = bs + (t & 1) * BN * BST;
            const bool dual = (t < 8);
            const int  kt   = dual ? t : t - 8;

            #pragma unroll
            for (int kk = 0; kk < 2; ++kk) {
                const int kc = kt * 32 + kk * 16 + lc2;   // col within D (even)
                uint32_t bfr[4][2];
                #pragma unroll
                for (int nf = 0; nf < 4; ++nf) {
                    int n = wn + nf * 8 + lr;
                    bfr[nf][0] = *(const uint32_t*)&bt[n * BST + kk * 16 + lc2];
                    bfr[nf][1] = *(const uint32_t*)&bt[n * BST + kk * 16 + lc2 + 8];
                }
                {   // A = xh
                    uint32_t afr[4][4];
                    #pragma unroll
                    for (int mf = 0; mf < 4; ++mf) {
                        int r = wm + mf * 16 + lr;
                        afr[mf][0] = *(const uint32_t*)&xh_s[r * AST + kc];
                        afr[mf][1] = *(const uint32_t*)&xh_s[(r + 8) * AST + kc];
                        afr[mf][2] = *(const uint32_t*)&xh_s[r * AST + kc + 8];
                        afr[mf][3] = *(const uint32_t*)&xh_s[(r + 8) * AST + kc + 8];
                    }
                    #pragma unroll
                    for (int mf = 0; mf < 4; ++mf)
                        #pragma unroll
                        for (int nf = 0; nf < 4; ++nf)
                            MMA16816(acc[mf][nf], afr[mf][0], afr[mf][1], afr[mf][2], afr[mf][3],
                                     bfr[nf][0], bfr[nf][1]);
                }
                if (dual) {  // A = xl against ch
                    uint32_t afr[4][4];
                    #pragma unroll
                    for (int mf = 0; mf < 4; ++mf) {
                        int r = wm + mf * 16 + lr;
                        afr[mf][0] = *(const uint32_t*)&xl_s[r * AST + kc];
                        afr[mf][1] = *(const uint32_t*)&xl_s[(r + 8) * AST + kc];
                        afr[mf][2] = *(const uint32_t*)&xl_s[r * AST + kc + 8];
                        afr[mf][3] = *(const uint32_t*)&xl_s[(r + 8) * AST + kc + 8];
                    }
                    #pragma unroll
                    for (int mf = 0; mf < 4; ++mf)
                        #pragma unroll
                        for (int nf = 0; nf < 4; ++nf)
                            MMA16816(acc[mf][nf], afr[mf][0], afr[mf][1], afr[mf][2], afr[mf][3],
                                     bfr[nf][0], bfr[nf][1]);
                }
            }
            __syncthreads();
        }

        // ---- distance + running argmin (reference rounding sequence) ----
        #pragma unroll
        for (int mf = 0; mf < 4; ++mf) {
            int r0 = wm + mf * 16 + lr;
            float ra0 = rowa[r0], ra1 = rowa[r0 + 8];
            #pragma unroll
            for (int nf = 0; nf < 4; ++nf) {
                #pragma unroll
                for (int cc = 0; cc < 2; ++cc) {
                    int n = wn + nf * 8 + lc2 + cc;
                    float bn = cbs[n];
                    int code = cbase + n;
                    float d0 = __fsub_rn(__fadd_rn(ra0, bn), __fmul_rn(2.0f, acc[mf][nf][cc]));
                    if (d0 < bestv[mf * 2 + 0]) { bestv[mf * 2 + 0] = d0; besti[mf * 2 + 0] = code; }
                    float d1 = __fsub_rn(__fadd_rn(ra1, bn), __fmul_rn(2.0f, acc[mf][nf][cc + 2]));
                    if (d1 < bestv[mf * 2 + 1]) { bestv[mf * 2 + 1] = d1; besti[mf * 2 + 1] = code; }
                }
            }
        }
    }

    // ---- cross-thread argmin reduction, lowest-index tie-break ----
    __syncthreads();
    #pragma unroll
    for (int mf = 0; mf < 4; ++mf) {
        int r0 = wm + mf * 16 + lr;
        int slot = (wid & 3) * 4 + (lane & 3);
        redv[r0 * 16 + slot] = bestv[mf * 2 + 0];
        redi[r0 * 16 + slot] = besti[mf * 2 + 0];
        redv[(r0 + 8) * 16 + slot] = bestv[mf * 2 + 1];
        redi[(r0 + 8) * 16 + slot] = besti[mf * 2 + 1];
    }
    __syncthreads();
    if (tid < BM) {
        float bv = redv[tid * 16]; int bi = redi[tid * 16];
        for (int t = 1; t < 16; ++t) {
            float v = redv[tid * 16 + t]; int ii = redi[tid * 16 + t];
            if (v < bv || (v == bv && ii < bi)) { bv = v; bi = ii; }
        }
        sel[tid] = bi;
        if (outidx) outidx[row0 + tid] = (float)bi;
    }
    __syncthreads();

    // ---- gather quantized rows, write, accumulate SSE ----
    float sse = 0.f;
    float4* oq = (float4*)outq;
    const float4* cg = (const float4*)cb;
    const float4* xg = (const float4*)x;
    for (int i = tid; i < BM * (D / 4); i += NTHREADS) {
        int r = i >> 6, c = i & 63;
        float4 q  = cg[(size_t)sel[r] * (D / 4) + c];
        float4 xv = xg[(size_t)(row0 + r) * (D / 4) + c];
        oq[(size_t)(row0 + r) * (D / 4) + c] = q;
        float dx = q.x - xv.x, dy = q.y - xv.y, dz = q.z - xv.z, dw = q.w - xv.w;
        sse += dx * dx + dy * dy + dz * dz + dw * dw;
    }
    #pragma unroll
    for (int o = 16; o; o >>= 1) sse += __shfl_xor_sync(0xffffffffu, sse, o);
    if ((tid & 31) == 0) atomicAdd(&g_sse, (double)sse);
}

__global__ void vq_fin(float* outloss) {
    *outloss = (float)((g_sse / 8388608.0) * 1.25);
}

extern "C" void kernel_launch(void* const* d_in, const int* in_sizes, int n_in,
                              void* d_out, int out_size) {
    const float* x  = (const float*)d_in[0];
    const float* cb = (const float*)d_in[1];
    if (n_in >= 2 && in_sizes[0] == K * D && in_sizes[1] == BT * D) {
        const float* t = x; x = cb; cb = t;
    }

    const size_t NQ = (size_t)BT * D;
    float* outq    = (float*)d_out;
    float* outidx  = nullptr;
    float* outloss = nullptr;
    if ((size_t)out_size >= NQ + BT) outidx = outq + NQ;
    if ((size_t)out_size >= NQ + BT + 1) outloss = outq + NQ + BT;
    else if ((size_t)out_size == NQ + 1) outloss = outq + NQ;

    __nv_bfloat16 *p_xh, *p_xl, *p_ch, *p_cl;
    cudaGetSymbolAddress((void**)&p_xh, g_xh);
    cudaGetSymbolAddress((void**)&p_xl, g_xl);
    cudaGetSymbolAddress((void**)&p_ch, g_ch);
    cudaGetSymbolAddress((void**)&p_cl, g_cl);

    size_t shmem = (size_t)(2 * BM * AST + 2 * BN * BST) * sizeof(__nv_bfloat16)
                 + (size_t)(BN + BM + BM * 16 + BM * 16 + BM) * sizeof(float) + 256;
    cudaFuncSetAttribute(vq_main, cudaFuncAttributeMaxDynamicSharedMemorySize, (int)shmem);

    vq_zero<<<1, 1>>>();
    vq_norms<<<K / 8, 256>>>(cb);
    vq_split<<<(BT * D + 255) / 256, 256>>>(x, p_xh, p_xl, BT * D);
    vq_split<<<(K * D + 255) / 256, 256>>>(cb, p_ch, p_cl, K * D);
    vq_main<<<BT / BM, NTHREADS, shmem>>>(x, cb, outq, outidx);
    if (outloss) vq_fin<<<1, 1>>>(outloss);
}

// round 4
// speedup vs baseline: 35.3123x; 5.6909x over previous
#include <cuda_runtime.h>
#include <cuda_bf16.h>
#include <cstdint>

#define D   256
#define K   8192
#define BT  32768
#define BM  128
#define NCT 64          // code tiles of 128
#define NCH 4           // k-chunks of 64 per D=256
#define NSTAGE 3
#define NTHREADS 256

// tcgen05 is arch-SPECIFIC (sm_103a); the build also runs a compute_103 PTX
// pass where those instructions are illegal. Compile the tcgen05 path only in
// the arch-specific pass; elsewhere compile a correct SIMT fallback.
#if defined(__CUDA_ARCH_FEAT_SM103_ALL) || defined(__CUDA_ARCH_FEAT_SM100_ALL) || defined(__CUDA_ARCH_SPECIFIC__)
#define VQ_TCGEN05 1
#else
#define VQ_TCGEN05 0
#endif

// ---- smem layout (bytes) ----
#define SM_A    0            // xh 64KB | xl 64KB (blocked SW128 image)
#define SM_B    131072       // 3 stages x 32KB (ch 16KB | cl 16KB)
#define SM_CBN  229376       // 128 floats
#define SM_SEL  229888       // 128 ints
#define SM_BAR  230400       // mbarriers + tmem ptr
#define SM_TOT  230528

#define OFF_FULL(s)   (SM_BAR + (s)*8)
#define OFF_EMPTY(s)  (SM_BAR + 24 + (s)*8)
#define OFF_DREADY(p) (SM_BAR + 48 + (p)*8)
#define OFF_EFREE(p)  (SM_BAR + 64 + (p)*8)
#define OFF_TPTR      (SM_BAR + 80)

// idesc: f32 accum, bf16 a/b, N=128, M=128
#define IDESC 0x08200490u

__device__ double g_sse;
__device__ float  g_cbnorm[K];
__device__ float  g_xnorm[BT];
__device__ unsigned char g_xa[(size_t)256 * 131072];  // [block][xh|xl] swizzled
__device__ unsigned char g_cb[(size_t)64 * 131072];   // [ctile][chunk][ch|cl] swizzled

// ================= PTX helpers =================
__device__ __forceinline__ uint32_t smem_u32(const void* p) {
    uint32_t a;
    asm("{ .reg .u64 t; cvta.to.shared.u64 t, %1; cvt.u32.u64 %0, t; }" : "=r"(a) : "l"(p));
    return a;
}

#if VQ_TCGEN05
__device__ __forceinline__ uint32_t elect_one() {
    uint32_t p;
    asm volatile("{\n\t.reg .pred p;\n\telect.sync _|p, 0xFFFFFFFF;\n\tselp.b32 %0, 1, 0, p;\n\t}" : "=r"(p));
    return p;
}
#define MBAR_INIT(a, n) asm volatile("mbarrier.init.shared.b64 [%0], %1;" :: "r"(a), "r"(n) : "memory")
#define MBAR_EXPECT(a, b) asm volatile("mbarrier.arrive.expect_tx.shared.b64 _, [%0], %1;" :: "r"(a), "r"(b) : "memory")
#define MBAR_ARRIVE(a) asm volatile("mbarrier.arrive.shared.b64 _, [%0];" :: "r"(a) : "memory")
#define MBAR_WAIT(a, ph) do {                                                      \
    uint32_t _m = (a), _p = (ph), _d;                                              \
    asm volatile("{\n\t.reg .pred p;\n\t"                                          \
        "mbarrier.try_wait.parity.acquire.cta.shared::cta.b64 p, [%1], %2;\n\t"    \
        "selp.b32 %0, 1, 0, p;\n\t}" : "=r"(_d) : "r"(_m), "r"(_p) : "memory");    \
    if (!_d) {                                                                     \
        asm volatile("{\n\t.reg .pred P1;\n\t"                                     \
        "WL_%=:\n\t"                                                               \
        "mbarrier.try_wait.parity.acquire.cta.shared::cta.b64 P1, [%0], %1, 0x989680;\n\t" \
        "@P1 bra.uni WD_%=;\n\tbra.uni WL_%=;\n\tWD_%=:\n\t}"                      \
        :: "r"(_m), "r"(_p) : "memory");                                           \
    }                                                                              \
} while (0)
#define TC_ALLOC(sp, n) asm volatile("tcgen05.alloc.cta_group::1.sync.aligned.shared::cta.b32 [%0], %1;" :: "r"(sp), "r"(n) : "memory")
#define TC_RELINQ() asm volatile("tcgen05.relinquish_alloc_permit.cta_group::1.sync.aligned;")
#define TC_DEALLOC(t, n) asm volatile("tcgen05.dealloc.cta_group::1.sync.aligned.b32 %0, %1;" :: "r"(t), "r"(n))
#define TC_COMMIT(a) asm volatile("tcgen05.commit.cta_group::1.mbarrier::arrive::one.shared::cluster.b64 [%0];" :: "r"(a) : "memory")
#define TC_FENCE_AFTER() asm volatile("tcgen05.fence::after_thread_sync;" ::: "memory")
#define TC_WAIT_LD() asm volatile("tcgen05.wait::ld.sync.aligned;" ::: "memory")
#define FENCE_ASYNC() asm volatile("fence.proxy.async.shared::cta;" ::: "memory")
#define BULK_CP(dst, src, mbar) \
    asm volatile("cp.async.bulk.shared::cta.global.mbarrier::complete_tx::bytes [%0], [%1], %2, [%3];" \
        :: "r"(dst), "l"(src), "r"(32768), "r"(mbar) : "memory")

static constexpr uint64_t DESC_BASE =
    (uint64_t(2) << 61) | (uint64_t(1) << 46) | (uint64_t(64) << 32) | (uint64_t(1) << 16);
#define MK_DESC(addr) (DESC_BASE | ((uint64_t)((addr) >> 4) & 0x3FFF))

__device__ __forceinline__ void mma_f16_ss(uint32_t d, uint64_t a, uint64_t b, uint32_t id, uint32_t en) {
    asm volatile("{\n\t.reg .pred p;\n\tsetp.ne.u32 p, %5, 0;\n\t"
        "tcgen05.mma.cta_group::1.kind::f16 [%0], %1, %2, %3, {%4,%4,%4,%4}, p;\n\t}"
        :: "r"(d), "l"(a), "l"(b), "r"(id), "r"(0u), "r"(en) : "memory");
}

#define LDTM32(r, addr) \
    asm volatile("tcgen05.ld.sync.aligned.32x32b.x32.b32 " \
        "{%0,%1,%2,%3,%4,%5,%6,%7,%8,%9,%10,%11,%12,%13,%14,%15," \
        "%16,%17,%18,%19,%20,%21,%22,%23,%24,%25,%26,%27,%28,%29,%30,%31}, [%32];" \
        : "=r"((r)[0]),"=r"((r)[1]),"=r"((r)[2]),"=r"((r)[3]),"=r"((r)[4]),"=r"((r)[5]),"=r"((r)[6]),"=r"((r)[7]), \
          "=r"((r)[8]),"=r"((r)[9]),"=r"((r)[10]),"=r"((r)[11]),"=r"((r)[12]),"=r"((r)[13]),"=r"((r)[14]),"=r"((r)[15]), \
          "=r"((r)[16]),"=r"((r)[17]),"=r"((r)[18]),"=r"((r)[19]),"=r"((r)[20]),"=r"((r)[21]),"=r"((r)[22]),"=r"((r)[23]), \
          "=r"((r)[24]),"=r"((r)[25]),"=r"((r)[26]),"=r"((r)[27]),"=r"((r)[28]),"=r"((r)[29]),"=r"((r)[30]),"=r"((r)[31]) \
        : "r"(addr))
#endif  // VQ_TCGEN05

// ================= pre-kernels =================
__global__ void vq_zero() { g_sse = 0.0; }

__global__ void vq_rownorm(const float* __restrict__ src, float* __restrict__ dst, int n) {
    int w = (blockIdx.x * blockDim.x + threadIdx.x) >> 5;
    int lane = threadIdx.x & 31;
    if (w >= n) return;
    const float* row = src + (size_t)w * D;
    float s = 0.f;
    for (int d = lane; d < D; d += 32) { float v = row[d]; s = __fmaf_rn(v, v, s); }
    #pragma unroll
    for (int o = 16; o; o >>= 1) s += __shfl_xor_sync(0xffffffffu, s, o);
    if (lane == 0) dst[w] = s;
}

__device__ __forceinline__ void split8(const float* src, __nv_bfloat16* h, __nv_bfloat16* l) {
    #pragma unroll
    for (int j = 0; j < 8; j++) {
        float v = src[j];
        __nv_bfloat16 hh = __float2bfloat16_rn(v);
        h[j] = hh;
        l[j] = __float2bfloat16_rn(v - __bfloat162float(hh));
    }
}

__global__ void vq_pack_x(const float* __restrict__ x) {
    int gid = blockIdx.x * blockDim.x + threadIdx.x;
    if (gid >= BT * D / 8) return;
    int row = gid >> 5, k = (gid & 31) * 8;
    __nv_bfloat16 h[8], l[8];
    split8(x + (size_t)row * D + k, h, l);
    int blk = row >> 7, r = row & 127;
    int tb = ((r >> 3) + (k >> 6) * 16) * 1024 + (r & 7) * 128 + (k & 63) * 2;
    int sw = tb ^ ((tb >> 3) & 0x70);
    size_t base = (size_t)blk * 131072;
    *(uint4*)(g_xa + base + sw) = *(uint4*)h;
    *(uint4*)(g_xa + base + 65536 + sw) = *(uint4*)l;
}

__global__ void vq_pack_c(const float* __restrict__ cb) {
    int gid = blockIdx.x * blockDim.x + threadIdx.x;
    if (gid >= K * D / 8) return;
    int code = gid >> 5, k = (gid & 31) * 8;
    __nv_bfloat16 h[8], l[8];
    split8(cb + (size_t)code * D + k, h, l);
    int ct = code >> 7, lc = code & 127;
    int tb = lc * 128 + (k & 63) * 2;
    int sw = tb ^ ((tb >> 3) & 0x70);
    size_t base = (size_t)ct * 131072 + (size_t)(k >> 6) * 32768;
    *(uint4*)(g_cb + base + sw) = *(uint4*)h;
    *(uint4*)(g_cb + base + 16384 + sw) = *(uint4*)l;
}

// ================= main kernel =================
__global__ __launch_bounds__(NTHREADS, 1) void vq_main(
    const float* __restrict__ x, const float* __restrict__ cb,
    float* __restrict__ outq, float* __restrict__ outidx)
{
    extern __shared__ char smem[];
    const int tid = threadIdx.x;
    const int wid = tid >> 5;
    const int blk = blockIdx.x;
    const int row0 = blk * BM;
    int* sel = (int*)(smem + SM_SEL);

#if VQ_TCGEN05
    const uint32_t sb = smem_u32(smem);
    float* cbn = (float*)(smem + SM_CBN);

    if (tid == 0) {
        #pragma unroll
        for (int s = 0; s < NSTAGE; ++s) { MBAR_INIT(sb + OFF_FULL(s), 1); MBAR_INIT(sb + OFF_EMPTY(s), 1); }
        #pragma unroll
        for (int p = 0; p < 2; ++p) { MBAR_INIT(sb + OFF_DREADY(p), 1); MBAR_INIT(sb + OFF_EFREE(p), 1); }
    }
    if (wid == 4) { TC_ALLOC(sb + OFF_TPTR, 256); TC_RELINQ(); }

    // resident A: flat copy of pre-swizzled image (128KB)
    {
        const uint4* src = (const uint4*)(g_xa + (size_t)blk * 131072);
        uint4* dst = (uint4*)(smem + SM_A);
        for (int i = tid; i < 131072 / 16; i += NTHREADS) dst[i] = src[i];
    }
    __syncthreads();
    FENCE_ASYNC();
    uint32_t tmem_base;
    asm volatile("ld.shared.b32 %0, [%1];" : "=r"(tmem_base) : "r"(sb + OFF_TPTR));

    if (wid == 4) {
        // ---------------- MMA warp ----------------
        if (elect_one()) {
            const uint64_t adh = MK_DESC(sb + SM_A);
            const uint64_t adl = MK_DESC(sb + SM_A + 65536);
            int i = 0;
            for (int t = 0; t < NCT; ++t) {
                const int p = t & 1;
                MBAR_WAIT(sb + OFF_EFREE(p), 1 ^ ((t >> 1) & 1));
                const uint32_t dbuf = tmem_base + p * 128;
                for (int c = 0; c < NCH; ++c) {
                    const int s = i % NSTAGE;
                    MBAR_WAIT(sb + OFF_FULL(s), (i / NSTAGE) & 1);
                    const uint64_t bch = MK_DESC(sb + SM_B + s * 32768);
                    const uint64_t bcl = bch + 1024;           // +16KB
                    const uint64_t ah = adh + c * 1024;
                    const uint64_t al = adl + c * 1024;
                    #pragma unroll
                    for (int ks = 0; ks < 4; ++ks)
                        mma_f16_ss(dbuf, ah + 2 * ks, bch + 2 * ks, IDESC, !(c == 0 && ks == 0));
                    #pragma unroll
                    for (int ks = 0; ks < 4; ++ks)
                        mma_f16_ss(dbuf, al + 2 * ks, bch + 2 * ks, IDESC, 1u);
                    #pragma unroll
                    for (int ks = 0; ks < 4; ++ks)
                        mma_f16_ss(dbuf, ah + 2 * ks, bcl + 2 * ks, IDESC, 1u);
                    TC_COMMIT(sb + OFF_EMPTY(s));
                    ++i;
                }
                TC_COMMIT(sb + OFF_DREADY(p));
            }
        }
    } else if (wid == 5) {
        // ---------------- producer warp ----------------
        if (elect_one()) {
            for (int i = 0; i < NCT * NCH; ++i) {
                const int s = i % NSTAGE;
                MBAR_WAIT(sb + OFF_EMPTY(s), 1 ^ ((i / NSTAGE) & 1));
                MBAR_EXPECT(sb + OFF_FULL(s), 32768);
                BULK_CP(sb + SM_B + s * 32768, (const void*)(g_cb + (size_t)i * 32768),
                        sb + OFF_FULL(s));
            }
        }
    } else if (wid < 4) {
        // ---------------- epilogue warps (thread tid owns row row0+tid) ----------------
        const float ra = g_xnorm[row0 + tid];
        float best = 3.4e38f; int bi = 0;
        for (int t = 0; t < NCT; ++t) {
            cbn[tid] = g_cbnorm[t * 128 + tid];
            asm volatile("bar.sync 1, 128;" ::: "memory");
            const int p = t & 1;
            MBAR_WAIT(sb + OFF_DREADY(p), (t >> 1) & 1);
            TC_FENCE_AFTER();
            const uint32_t dbuf = tmem_base + p * 128;
            #pragma unroll
            for (int cc = 0; cc < 4; ++cc) {
                uint32_t v[32];
                LDTM32(v, dbuf + cc * 32);
                TC_WAIT_LD();
                #pragma unroll
                for (int j = 0; j < 32; ++j) {
                    const int col = cc * 32 + j;
                    float dist = __fsub_rn(__fadd_rn(ra, cbn[col]),
                                           __fmul_rn(2.0f, __uint_as_float(v[j])));
                    if (dist < best) { best = dist; bi = t * 128 + col; }
                }
            }
            asm volatile("bar.sync 1, 128;" ::: "memory");
            if (tid == 0) MBAR_ARRIVE(sb + OFF_EFREE(p));
        }
        sel[tid] = bi;
        if (outidx) outidx[row0 + tid] = (float)bi;
    }

    __syncthreads();
    if (wid == 4) TC_DEALLOC(tmem_base, 256);

#else  // ---------------- SIMT fallback (non-arch-specific compile pass) ----------------
    float* xs = (float*)smem;                 // [BM][257]
    if (tid < BM) {
        const float* xr = x + (size_t)(row0 + tid) * D;
        for (int c = 0; c < D; ++c) xs[tid * 257 + c] = xr[c];
    }
    __syncthreads();
    if (tid < BM) {
        const float* xr = xs + tid * 257;
        const float ra = g_xnorm[row0 + tid];
        float best = 3.4e38f; int bi = 0;
        for (int code = 0; code < K; ++code) {
            const float* cr = cb + (size_t)code * D;
            float dot = 0.f;
            for (int d = 0; d < D; ++d) dot = __fmaf_rn(xr[d], cr[d], dot);
            float dist = __fsub_rn(__fadd_rn(ra, g_cbnorm[code]), __fmul_rn(2.0f, dot));
            if (dist < best) { best = dist; bi = code; }
        }
        sel[tid] = bi;
        if (outidx) outidx[row0 + tid] = (float)bi;
    }
    __syncthreads();
#endif

    // ---- gather quantized rows, write, accumulate SSE (all 256 threads) ----
    float sse = 0.f;
    float4* oq = (float4*)outq;
    const float4* cg = (const float4*)cb;
    const float4* xg = (const float4*)x;
    for (int i = tid; i < BM * (D / 4); i += NTHREADS) {
        int r = i >> 6, c = i & 63;
        float4 q  = cg[(size_t)sel[r] * (D / 4) + c];
        float4 xv = xg[(size_t)(row0 + r) * (D / 4) + c];
        oq[(size_t)(row0 + r) * (D / 4) + c] = q;
        float dx = q.x - xv.x, dy = q.y - xv.y, dz = q.z - xv.z, dw = q.w - xv.w;
        sse += dx * dx + dy * dy + dz * dz + dw * dw;
    }
    #pragma unroll
    for (int o = 16; o; o >>= 1) sse += __shfl_xor_sync(0xffffffffu, sse, o);
    if ((tid & 31) == 0) atomicAdd(&g_sse, (double)sse);
}

__global__ void vq_fin(float* outloss) {
    *outloss = (float)((g_sse / 8388608.0) * 1.25);
}

extern "C" void kernel_launch(void* const* d_in, const int* in_sizes, int n_in,
                              void* d_out, int out_size) {
    const float* x  = (const float*)d_in[0];
    const float* cb = (const float*)d_in[1];
    if (n_in >= 2 && in_sizes[0] == K * D && in_sizes[1] == BT * D) {
        const float* t = x; x = cb; cb = t;
    }

    const size_t NQ = (size_t)BT * D;
    float* outq    = (float*)d_out;
    float* outidx  = nullptr;
    float* outloss = nullptr;
    if ((size_t)out_size >= NQ + BT) outidx = outq + NQ;
    if ((size_t)out_size >= NQ + BT + 1) outloss = outq + NQ + BT;
    else if ((size_t)out_size == NQ + 1) outloss = outq + NQ;

    float *p_xn, *p_cn;
    cudaGetSymbolAddress((void**)&p_xn, g_xnorm);
    cudaGetSymbolAddress((void**)&p_cn, g_cbnorm);

    cudaFuncSetAttribute(vq_main, cudaFuncAttributeMaxDynamicSharedMemorySize, SM_TOT);

    vq_zero<<<1, 1>>>();
    vq_rownorm<<<BT / 8, 256>>>(x, p_xn, BT);
    vq_rownorm<<<K / 8, 256>>>(cb, p_cn, K);
    vq_pack_x<<<(BT * D / 8) / 256, 256>>>(x);
    vq_pack_c<<<(K * D / 8) / 256, 256>>>(cb);
    vq_main<<<BT / BM, NTHREADS, SM_TOT>>>(x, cb, outq, outidx);
    if (outloss) vq_fin<<<1, 1>>>(outloss);
}

// round 6
// speedup vs baseline: 35.6509x; 1.0096x over previous
#include <cuda_runtime.h>
#include <cuda_bf16.h>
#include <cstdint>

#define D   256
#define K   8192
#define BT  32768
#define BM  128
#define NCT 64          // code tiles of 128
#define NCH 4           // k-chunks of 64 per D=256
#define NSTAGE 4
#define NTHREADS 256

#if defined(__CUDA_ARCH_FEAT_SM103_ALL) || defined(__CUDA_ARCH_FEAT_SM100_ALL) || defined(__CUDA_ARCH_SPECIFIC__)
#define VQ_TCGEN05 1
#else
#define VQ_TCGEN05 0
#endif

// ---- smem layout (bytes) ----
#define SM_A    0            // xh 64KB | xl 64KB (blocked SW128 image, this CTA's 128 rows)
#define SM_B    131072       // 4 stages x 16KB (ch 8KB | cl 8KB), this CTA's 64-code half
#define SM_CBN  196608       // 128 floats
#define SM_SEL  197120       // 128 ints
#define SM_BAR  197632       // mbarriers + tmem ptr
#define SM_TOT  197888

#define OFF_FULL(s)   (SM_BAR + (s)*8)
#define OFF_EMPTY(s)  (SM_BAR + 32 + (s)*8)
#define OFF_FULLX(s)  (SM_BAR + 64 + (s)*8)
#define OFF_DREADY(p) (SM_BAR + 96 + (p)*8)
#define OFF_EFREE(p)  (SM_BAR + 112 + (p)*8)
#define OFF_TPTR      (SM_BAR + 128)

// idesc: f32 accum, bf16 a/b, N=128, M=256 (cta_group::2)
#define IDESC2 0x10200490u

__device__ double g_sse;
__device__ float  g_cbnorm[K];
__device__ float  g_xnorm[BT];
__device__ unsigned char g_xa[(size_t)256 * 131072];  // [block][xh|xl] swizzled
__device__ unsigned char g_cb[(size_t)512 * 16384];   // [ctile][chunk][half][ch|cl] swizzled

// ================= PTX helpers =================
__device__ __forceinline__ uint32_t smem_u32(const void* p) {
    uint32_t a;
    asm("{ .reg .u64 t; cvta.to.shared.u64 t, %1; cvt.u32.u64 %0, t; }" : "=r"(a) : "l"(p));
    return a;
}

#if VQ_TCGEN05
__device__ __forceinline__ uint32_t elect_one() {
    uint32_t p;
    asm volatile("{\n\t.reg .pred p;\n\telect.sync _|p, 0xFFFFFFFF;\n\tselp.b32 %0, 1, 0, p;\n\t}" : "=r"(p));
    return p;
}
__device__ __forceinline__ uint32_t ctarank() {
    uint32_t r; asm("mov.u32 %0, %%cluster_ctarank;" : "=r"(r)); return r;
}
#define MBAR_INIT(a, n) asm volatile("mbarrier.init.shared.b64 [%0], %1;" :: "r"(a), "r"(n) : "memory")
#define MBAR_EXPECT(a, b) asm volatile("mbarrier.arrive.expect_tx.shared.b64 _, [%0], %1;" :: "r"(a), "r"(b) : "memory")
#define MBAR_ARRIVE(a) asm volatile("mbarrier.arrive.shared.b64 _, [%0];" :: "r"(a) : "memory")
#define MBAR_ARRIVE_RANK0(a) \
    asm volatile("{\n\t.reg .b32 ra;\n\tmapa.shared::cluster.u32 ra, %0, %1;\n\t" \
        "mbarrier.arrive.shared::cluster.b64 _, [ra];\n\t}" :: "r"(a), "r"(0) : "memory")
#define MBAR_WAIT(a, ph) do {                                                      \
    uint32_t _m = (a), _p = (ph), _d;                                              \
    asm volatile("{\n\t.reg .pred p;\n\t"                                          \
        "mbarrier.try_wait.parity.acquire.cta.shared::cta.b64 p, [%1], %2;\n\t"    \
        "selp.b32 %0, 1, 0, p;\n\t}" : "=r"(_d) : "r"(_m), "r"(_p) : "memory");    \
    if (!_d) {                                                                     \
        asm volatile("{\n\t.reg .pred P1;\n\t"                                     \
        "WL_%=:\n\t"                                                               \
        "mbarrier.try_wait.parity.acquire.cta.shared::cta.b64 P1, [%0], %1, 0x989680;\n\t" \
        "@P1 bra.uni WD_%=;\n\tbra.uni WL_%=;\n\tWD_%=:\n\t}"                      \
        :: "r"(_m), "r"(_p) : "memory");                                           \
    }                                                                              \
} while (0)
#define TC_ALLOC2(sp, n) asm volatile("tcgen05.alloc.cta_group::2.sync.aligned.shared::cta.b32 [%0], %1;" :: "r"(sp), "r"(n) : "memory")
#define TC_RELINQ2() asm volatile("tcgen05.relinquish_alloc_permit.cta_group::2.sync.aligned;")
#define TC_DEALLOC2(t, n) asm volatile("tcgen05.dealloc.cta_group::2.sync.aligned.b32 %0, %1;" :: "r"(t), "r"(n))
#define TC_COMMIT_MC(a) \
    asm volatile("tcgen05.commit.cta_group::2.mbarrier::arrive::one.shared::cluster.multicast::cluster.b64 [%0], %1;" \
        :: "r"(a), "h"((unsigned short)0x3) : "memory")
#define TC_FENCE_AFTER() asm volatile("tcgen05.fence::after_thread_sync;" ::: "memory")
#define TC_WAIT_LD() asm volatile("tcgen05.wait::ld.sync.aligned;" ::: "memory")
#define FENCE_ASYNC() asm volatile("fence.proxy.async.shared::cta;" ::: "memory")
#define CLUSTER_SYNC() do { \
    asm volatile("barrier.cluster.arrive.aligned;" ::: "memory"); \
    asm volatile("barrier.cluster.wait.aligned;" ::: "memory"); } while (0)
#define BULK_CP(dst, src, bytes, mbar) \
    asm volatile("cp.async.bulk.shared::cta.global.mbarrier::complete_tx::bytes [%0], [%1], %2, [%3];" \
        :: "r"(dst), "l"(src), "r"(bytes), "r"(mbar) : "memory")

static constexpr uint64_t DESC_BASE =
    (uint64_t(2) << 61) | (uint64_t(1) << 46) | (uint64_t(64) << 32) | (uint64_t(1) << 16);
#define MK_DESC(addr) (DESC_BASE | ((uint64_t)((addr) >> 4) & 0x3FFF))

__device__ __forceinline__ void mma_f16_ss2(uint32_t d, uint64_t a, uint64_t b, uint32_t id, uint32_t en) {
    asm volatile("{\n\t.reg .pred p;\n\tsetp.ne.u32 p, %5, 0;\n\t"
        "tcgen05.mma.cta_group::2.kind::f16 [%0], %1, %2, %3, {%4,%4,%4,%4,%4,%4,%4,%4}, p;\n\t}"
        :: "r"(d), "l"(a), "l"(b), "r"(id), "r"(0u), "r"(en) : "memory");
}

#define LDTM32(r, addr) \
    asm volatile("tcgen05.ld.sync.aligned.32x32b.x32.b32 " \
        "{%0,%1,%2,%3,%4,%5,%6,%7,%8,%9,%10,%11,%12,%13,%14,%15," \
        "%16,%17,%18,%19,%20,%21,%22,%23,%24,%25,%26,%27,%28,%29,%30,%31}, [%32];" \
        : "=r"((r)[0]),"=r"((r)[1]),"=r"((r)[2]),"=r"((r)[3]),"=r"((r)[4]),"=r"((r)[5]),"=r"((r)[6]),"=r"((r)[7]), \
          "=r"((r)[8]),"=r"((r)[9]),"=r"((r)[10]),"=r"((r)[11]),"=r"((r)[12]),"=r"((r)[13]),"=r"((r)[14]),"=r"((r)[15]), \
          "=r"((r)[16]),"=r"((r)[17]),"=r"((r)[18]),"=r"((r)[19]),"=r"((r)[20]),"=r"((r)[21]),"=r"((r)[22]),"=r"((r)[23]), \
          "=r"((r)[24]),"=r"((r)[25]),"=r"((r)[26]),"=r"((r)[27]),"=r"((r)[28]),"=r"((r)[29]),"=r"((r)[30]),"=r"((r)[31]) \
        : "r"(addr))
#endif  // VQ_TCGEN05

// ================= pre-kernels =================
__global__ void vq_zero() { g_sse = 0.0; }

__global__ void vq_rownorm(const float* __restrict__ src, float* __restrict__ dst, int n) {
    int w = (blockIdx.x * blockDim.x + threadIdx.x) >> 5;
    int lane = threadIdx.x & 31;
    if (w >= n) return;
    const float* row = src + (size_t)w * D;
    float s = 0.f;
    for (int d = lane; d < D; d += 32) { float v = row[d]; s = __fmaf_rn(v, v, s); }
    #pragma unroll
    for (int o = 16; o; o >>= 1) s += __shfl_xor_sync(0xffffffffu, s, o);
    if (lane == 0) dst[w] = s;
}

__device__ __forceinline__ void split8(const float* src, __nv_bfloat16* h, __nv_bfloat16* l) {
    #pragma unroll
    for (int j = 0; j < 8; j++) {
        float v = src[j];
        __nv_bfloat16 hh = __float2bfloat16_rn(v);
        h[j] = hh;
        l[j] = __float2bfloat16_rn(v - __bfloat162float(hh));
    }
}

__global__ void vq_pack_x(const float* __restrict__ x) {
    int gid = blockIdx.x * blockDim.x + threadIdx.x;
    if (gid >= BT * D / 8) return;
    int row = gid >> 5, k = (gid & 31) * 8;
    __nv_bfloat16 h[8], l[8];
    split8(x + (size_t)row * D + k, h, l);
    int blk = row >> 7, r = row & 127;
    int tb = ((r >> 3) + (k >> 6) * 16) * 1024 + (r & 7) * 128 + (k & 63) * 2;
    int sw = tb ^ ((tb >> 3) & 0x70);
    size_t base = (size_t)blk * 131072;
    *(uint4*)(g_xa + base + sw) = *(uint4*)h;
    *(uint4*)(g_xa + base + 65536 + sw) = *(uint4*)l;
}

// codebook packed as [ctile][chunk][half]: 16KB units of [ch 8KB | cl 8KB],
// half = 64 codes (cg2 B is split N/2 per CTA)
__global__ void vq_pack_c(const float* __restrict__ cb) {
    int gid = blockIdx.x * blockDim.x + threadIdx.x;
    if (gid >= K * D / 8) return;
    int code = gid >> 5, k = (gid & 31) * 8;
    __nv_bfloat16 h[8], l[8];
    split8(cb + (size_t)code * D + k, h, l);
    int ct = code >> 7, lc = code & 127;
    int half = lc >> 6, lrow = lc & 63;
    int tb = lrow * 128 + (k & 63) * 2;
    int sw = tb ^ ((tb >> 3) & 0x70);
    size_t base = (size_t)(((ct * NCH + (k >> 6)) * 2) + half) * 16384;
    *(uint4*)(g_cb + base + sw) = *(uint4*)h;
    *(uint4*)(g_cb + base + 8192 + sw) = *(uint4*)l;
}

// ================= main kernel =================
__global__ __launch_bounds__(NTHREADS, 1) __cluster_dims__(2, 1, 1)
void vq_main(const float* __restrict__ x, const float* __restrict__ cb,
             float* __restrict__ outq, float* __restrict__ outidx)
{
    extern __shared__ char smem[];
    const int tid = threadIdx.x;
    const int wid = tid >> 5;
    const int blk = blockIdx.x;
    const int row0 = blk * BM;
    int* sel = (int*)(smem + SM_SEL);

#if VQ_TCGEN05
    const uint32_t sb = smem_u32(smem);
    const uint32_t rank = ctarank();
    float* cbn = (float*)(smem + SM_CBN);

    if (tid == 0) {
        #pragma unroll
        for (int s = 0; s < NSTAGE; ++s) {
            MBAR_INIT(sb + OFF_FULL(s), 1);
            MBAR_INIT(sb + OFF_EMPTY(s), 1);
            MBAR_INIT(sb + OFF_FULLX(s), 2);
        }
        #pragma unroll
        for (int p = 0; p < 2; ++p) { MBAR_INIT(sb + OFF_DREADY(p), 1); MBAR_INIT(sb + OFF_EFREE(p), 2); }
    }
    if (wid == 4) { TC_ALLOC2(sb + OFF_TPTR, 256); TC_RELINQ2(); }

    // resident A: flat copy of this CTA's pre-swizzled image (128KB)
    {
        const uint4* src = (const uint4*)(g_xa + (size_t)blk * 131072);
        uint4* dst = (uint4*)(smem + SM_A);
        for (int i = tid; i < 131072 / 16; i += NTHREADS) dst[i] = src[i];
    }
    FENCE_ASYNC();
    __syncthreads();
    uint32_t tmem_base;
    asm volatile("ld.shared.b32 %0, [%1];" : "=r"(tmem_base) : "r"(sb + OFF_TPTR));
    CLUSTER_SYNC();   // all mbarriers init'd + A tiles visible before cross-CTA traffic

    if (wid == 4) {
        // ---------------- MMA warp (leader only issues) ----------------
        if (rank == 0 && elect_one()) {
            const uint64_t adh = MK_DESC(sb + SM_A);
            const uint64_t adl = MK_DESC(sb + SM_A + 65536);
            int i = 0;
            for (int t = 0; t < NCT; ++t) {
                const int p = t & 1;
                MBAR_WAIT(sb + OFF_EFREE(p), 1 ^ ((t >> 1) & 1));
                const uint32_t dbuf = tmem_base + p * 128;
                for (int c = 0; c < NCH; ++c) {
                    const int s = i & (NSTAGE - 1);
                    MBAR_WAIT(sb + OFF_FULLX(s), (i >> 2) & 1);
                    const uint64_t bch = MK_DESC(sb + SM_B + s * 16384);
                    const uint64_t bcl = bch + 512;            // +8KB
                    const uint64_t ah = adh + c * 1024;
                    const uint64_t al = adl + c * 1024;
                    #pragma unroll
                    for (int ks = 0; ks < 4; ++ks)
                        mma_f16_ss2(dbuf, ah + 2 * ks, bch + 2 * ks, IDESC2, !(c == 0 && ks == 0));
                    #pragma unroll
                    for (int ks = 0; ks < 4; ++ks)
                        mma_f16_ss2(dbuf, al + 2 * ks, bch + 2 * ks, IDESC2, 1u);
                    #pragma unroll
                    for (int ks = 0; ks < 4; ++ks)
                        mma_f16_ss2(dbuf, ah + 2 * ks, bcl + 2 * ks, IDESC2, 1u);
                    TC_COMMIT_MC(sb + OFF_EMPTY(s));   // both CTAs' EMPTY(s)
                    ++i;
                }
                TC_COMMIT_MC(sb + OFF_DREADY(p));      // both CTAs' DREADY(p)
            }
        }
    } else if (wid == 5) {
        // ---------------- producer warp (both CTAs; each loads its N/2 half) ----------------
        if (elect_one()) {
            for (int i = 0; i < NCT * NCH; ++i) {
                const int s = i & (NSTAGE - 1);
                MBAR_WAIT(sb + OFF_EMPTY(s), 1 ^ ((i >> 2) & 1));
                MBAR_EXPECT(sb + OFF_FULL(s), 16384);
                BULK_CP(sb + SM_B + s * 16384,
                        (const void*)(g_cb + (size_t)(2 * i + rank) * 16384),
                        16384, sb + OFF_FULL(s));
            }
        }
    } else if (wid == 6) {
        // ---------------- relay warp: local FULL -> leader's FULLX ----------------
        if (elect_one()) {
            for (int i = 0; i < NCT * NCH; ++i) {
                const int s = i & (NSTAGE - 1);
                MBAR_WAIT(sb + OFF_FULL(s), (i >> 2) & 1);
                if (rank == 0) { MBAR_ARRIVE(sb + OFF_FULLX(s)); }
                else           { MBAR_ARRIVE_RANK0(sb + OFF_FULLX(s)); }
            }
        }
    } else if (wid < 4) {
        // ---------------- epilogue warps (thread tid owns row row0+tid) ----------------
        const float ra = g_xnorm[row0 + tid];
        float best = 3.4e38f; int bi = 0;
        for (int t = 0; t < NCT; ++t) {
            cbn[tid] = g_cbnorm[t * 128 + tid];
            asm volatile("bar.sync 1, 128;" ::: "memory");
            const int p = t & 1;
            MBAR_WAIT(sb + OFF_DREADY(p), (t >> 1) & 1);
            TC_FENCE_AFTER();
            const uint32_t dbuf = tmem_base + p * 128;
            #pragma unroll
            for (int cc = 0; cc < 4; ++cc) {
                uint32_t v[32];
                LDTM32(v, dbuf + cc * 32);
                TC_WAIT_LD();
                #pragma unroll
                for (int j = 0; j < 32; ++j) {
                    const int col = cc * 32 + j;
                    float dist = __fsub_rn(__fadd_rn(ra, cbn[col]),
                                           __fmul_rn(2.0f, __uint_as_float(v[j])));
                    if (dist < best) { best = dist; bi = t * 128 + col; }
                }
            }
            asm volatile("bar.sync 1, 128;" ::: "memory");
            if (tid == 0) {
                if (rank == 0) { MBAR_ARRIVE(sb + OFF_EFREE(p)); }
                else           { MBAR_ARRIVE_RANK0(sb + OFF_EFREE(p)); }
            }
        }
        sel[tid] = bi;
        if (outidx) outidx[row0 + tid] = (float)bi;
    }

    __syncthreads();
    CLUSTER_SYNC();                 // both CTAs fully done with TMEM/peer SMEM
    if (wid == 4) TC_DEALLOC2(tmem_base, 256);

#else  // ---------------- SIMT fallback (non-arch-specific compile pass) ----------------
    float* xs = (float*)smem;                 // [BM][257]
    if (tid < BM) {
        const float* xr = x + (size_t)(row0 + tid) * D;
        for (int c = 0; c < D; ++c) xs[tid * 257 + c] = xr[c];
    }
    __syncthreads();
    if (tid < BM) {
        const float* xr = xs + tid * 257;
        const float ra = g_xnorm[row0 + tid];
        float best = 3.4e38f; int bi = 0;
        for (int code = 0; code < K; ++code) {
            const float* cr = cb + (size_t)code * D;
            float dot = 0.f;
            for (int d = 0; d < D; ++d) dot = __fmaf_rn(xr[d], cr[d], dot);
            float dist = __fsub_rn(__fadd_rn(ra, g_cbnorm[code]), __fmul_rn(2.0f, dot));
            if (dist < best) { best = dist; bi = code; }
        }
        sel[tid] = bi;
        if (outidx) outidx[row0 + tid] = (float)bi;
    }
    __syncthreads();
#endif

    // ---- gather quantized rows, write, accumulate SSE (all 256 threads) ----
    float sse = 0.f;
    float4* oq = (float4*)outq;
    const float4* cg = (const float4*)cb;
    const float4* xg = (const float4*)x;
    for (int i = tid; i < BM * (D / 4); i += NTHREADS) {
        int r = i >> 6, c = i & 63;
        float4 q  = cg[(size_t)sel[r] * (D / 4) + c];
        float4 xv = xg[(size_t)(row0 + r) * (D / 4) + c];
        oq[(size_t)(row0 + r) * (D / 4) + c] = q;
        float dx = q.x - xv.x, dy = q.y - xv.y, dz = q.z - xv.z, dw = q.w - xv.w;
        sse += dx * dx + dy * dy + dz * dz + dw * dw;
    }
    #pragma unroll
    for (int o = 16; o; o >>= 1) sse += __shfl_xor_sync(0xffffffffu, sse, o);
    if ((tid & 31) == 0) atomicAdd(&g_sse, (double)sse);
}

__global__ void vq_fin(float* outloss) {
    *outloss = (float)((g_sse / 8388608.0) * 1.25);
}

extern "C" void kernel_launch(void* const* d_in, const int* in_sizes, int n_in,
                              void* d_out, int out_size) {
    const float* x  = (const float*)d_in[0];
    const float* cb = (const float*)d_in[1];
    if (n_in >= 2 && in_sizes[0] == K * D && in_sizes[1] == BT * D) {
        const float* t = x; x = cb; cb = t;
    }

    const size_t NQ = (size_t)BT * D;
    float* outq    = (float*)d_out;
    float* outidx  = nullptr;
    float* outloss = nullptr;
    if ((size_t)out_size >= NQ + BT) outidx = outq + NQ;
    if ((size_t)out_size >= NQ + BT + 1) outloss = outq + NQ + BT;
    else if ((size_t)out_size == NQ + 1) outloss = outq + NQ;

    float *p_xn, *p_cn;
    cudaGetSymbolAddress((void**)&p_xn, g_xnorm);
    cudaGetSymbolAddress((void**)&p_cn, g_cbnorm);

    cudaFuncSetAttribute(vq_main, cudaFuncAttributeMaxDynamicSharedMemorySize, SM_TOT);

    vq_zero<<<1, 1>>>();
    vq_rownorm<<<BT / 8, 256>>>(x, p_xn, BT);
    vq_rownorm<<<K / 8, 256>>>(cb, p_cn, K);
    vq_pack_x<<<(BT * D / 8) / 256, 256>>>(x);
    vq_pack_c<<<(K * D / 8) / 256, 256>>>(cb);
    vq_main<<<BT / BM, NTHREADS, SM_TOT>>>(x, cb, outq, outidx);
    if (outloss) vq_fin<<<1, 1>>>(outloss);
}

// round 7
// speedup vs baseline: 40.4025x; 1.1333x over previous
#include <cuda_runtime.h>
#include <cuda_bf16.h>
#include <cstdint>

#define D   256
#define K   8192
#define BT  32768
#define BM  128
#define NCT 64          // code tiles of 128
#define NCH 4           // k-chunks of 64 per D=256
#define NSTAGE 4
#define NTHREADS 384

#if defined(__CUDA_ARCH_FEAT_SM103_ALL) || defined(__CUDA_ARCH_FEAT_SM100_ALL) || defined(__CUDA_ARCH_SPECIFIC__)
#define VQ_TCGEN05 1
#else
#define VQ_TCGEN05 0
#endif

// ---- smem layout (bytes) ----
#define SM_A    0            // xh 64KB | xl 64KB (blocked SW128 image, this CTA's 128 rows)
#define SM_B    131072       // 4 stages x 16KB (ch 8KB | cl 8KB), this CTA's 64-code half
#define SM_CBN  196608       // all 8192 codebook norms (32KB)
#define SM_SEL  229376       // 128 ints
#define SM_ROWA 229888       // 128 floats (row norms)
#define SM_BAR  230400       // mbarriers + tmem ptr
#define SM_TOT  230656

#define OFF_FULL(s)   (SM_BAR + (s)*8)
#define OFF_EMPTY(s)  (SM_BAR + 32 + (s)*8)
#define OFF_FULLX(s)  (SM_BAR + 64 + (s)*8)
#define OFF_DREADY(p) (SM_BAR + 96 + (p)*8)
#define OFF_EFREE(p)  (SM_BAR + 128 + (p)*8)
#define OFF_TPTR      (SM_BAR + 160)

// idesc: f32 accum, bf16 a/b, N=128, M=256 (cta_group::2)
#define IDESC2 0x10200490u

__device__ double g_sse;
__device__ float  g_cbnorm[K];
__device__ unsigned char g_cb[(size_t)512 * 16384];   // [ctile][chunk][half][ch|cl] swizzled

// ================= helpers =================
__device__ __forceinline__ uint32_t smem_u32(const void* p) {
    uint32_t a;
    asm("{ .reg .u64 t; cvta.to.shared.u64 t, %1; cvt.u32.u64 %0, t; }" : "=r"(a) : "l"(p));
    return a;
}

// split 8 fp32 -> hi/lo bf16 packed words; also accumulates sum of squares of originals
__device__ __forceinline__ void split_pack8(const float* v, uint4& H, uint4& L, float& ss) {
    uint32_t hw[4], lw[4];
    #pragma unroll
    for (int k = 0; k < 4; k++) {
        float a = v[2 * k], b = v[2 * k + 1];
        ss = __fmaf_rn(a, a, ss); ss = __fmaf_rn(b, b, ss);
        __nv_bfloat16 ha = __float2bfloat16_rn(a);
        __nv_bfloat16 hb = __float2bfloat16_rn(b);
        float la = a - __bfloat162float(ha);
        float lb = b - __bfloat162float(hb);
        hw[k] = (uint32_t)__bfloat16_as_ushort(ha) | ((uint32_t)__bfloat16_as_ushort(hb) << 16);
        lw[k] = (uint32_t)__bfloat16_as_ushort(__float2bfloat16_rn(la))
              | ((uint32_t)__bfloat16_as_ushort(__float2bfloat16_rn(lb)) << 16);
    }
    H = make_uint4(hw[0], hw[1], hw[2], hw[3]);
    L = make_uint4(lw[0], lw[1], lw[2], lw[3]);
}

#if VQ_TCGEN05
__device__ __forceinline__ uint32_t elect_one() {
    uint32_t p;
    asm volatile("{\n\t.reg .pred p;\n\telect.sync _|p, 0xFFFFFFFF;\n\tselp.b32 %0, 1, 0, p;\n\t}" : "=r"(p));
    return p;
}
__device__ __forceinline__ uint32_t ctarank() {
    uint32_t r; asm("mov.u32 %0, %%cluster_ctarank;" : "=r"(r)); return r;
}
#define MBAR_INIT(a, n) asm volatile("mbarrier.init.shared.b64 [%0], %1;" :: "r"(a), "r"(n) : "memory")
#define MBAR_EXPECT(a, b) asm volatile("mbarrier.arrive.expect_tx.shared.b64 _, [%0], %1;" :: "r"(a), "r"(b) : "memory")
#define MBAR_ARRIVE(a) asm volatile("mbarrier.arrive.shared.b64 _, [%0];" :: "r"(a) : "memory")
#define MBAR_ARRIVE_RANK0(a) \
    asm volatile("{\n\t.reg .b32 ra;\n\tmapa.shared::cluster.u32 ra, %0, %1;\n\t" \
        "mbarrier.arrive.shared::cluster.b64 _, [ra];\n\t}" :: "r"(a), "r"(0) : "memory")
#define MBAR_WAIT(a, ph) do {                                                      \
    uint32_t _m = (a), _p = (ph), _d;                                              \
    asm volatile("{\n\t.reg .pred p;\n\t"                                          \
        "mbarrier.try_wait.parity.acquire.cta.shared::cta.b64 p, [%1], %2;\n\t"    \
        "selp.b32 %0, 1, 0, p;\n\t}" : "=r"(_d) : "r"(_m), "r"(_p) : "memory");    \
    if (!_d) {                                                                     \
        asm volatile("{\n\t.reg .pred P1;\n\t"                                     \
        "WL_%=:\n\t"                                                               \
        "mbarrier.try_wait.parity.acquire.cta.shared::cta.b64 P1, [%0], %1, 0x989680;\n\t" \
        "@P1 bra.uni WD_%=;\n\tbra.uni WL_%=;\n\tWD_%=:\n\t}"                      \
        :: "r"(_m), "r"(_p) : "memory");                                           \
    }                                                                              \
} while (0)
#define TC_ALLOC2(sp, n) asm volatile("tcgen05.alloc.cta_group::2.sync.aligned.shared::cta.b32 [%0], %1;" :: "r"(sp), "r"(n) : "memory")
#define TC_RELINQ2() asm volatile("tcgen05.relinquish_alloc_permit.cta_group::2.sync.aligned;")
#define TC_DEALLOC2(t, n) asm volatile("tcgen05.dealloc.cta_group::2.sync.aligned.b32 %0, %1;" :: "r"(t), "r"(n))
#define TC_COMMIT_MC(a) \
    asm volatile("tcgen05.commit.cta_group::2.mbarrier::arrive::one.shared::cluster.multicast::cluster.b64 [%0], %1;" \
        :: "r"(a), "h"((unsigned short)0x3) : "memory")
#define TC_FENCE_AFTER() asm volatile("tcgen05.fence::after_thread_sync;" ::: "memory")
#define TC_WAIT_LD() asm volatile("tcgen05.wait::ld.sync.aligned;" ::: "memory")
#define FENCE_ASYNC() asm volatile("fence.proxy.async.shared::cta;" ::: "memory")
#define CLUSTER_SYNC() do { \
    asm volatile("barrier.cluster.arrive.aligned;" ::: "memory"); \
    asm volatile("barrier.cluster.wait.aligned;" ::: "memory"); } while (0)
#define BULK_CP(dst, src, bytes, mbar) \
    asm volatile("cp.async.bulk.shared::cta.global.mbarrier::complete_tx::bytes [%0], [%1], %2, [%3];" \
        :: "r"(dst), "l"(src), "r"(bytes), "r"(mbar) : "memory")

static constexpr uint64_t DESC_BASE =
    (uint64_t(2) << 61) | (uint64_t(1) << 46) | (uint64_t(64) << 32) | (uint64_t(1) << 16);
#define MK_DESC(addr) (DESC_BASE | ((uint64_t)((addr) >> 4) & 0x3FFF))

__device__ __forceinline__ void mma_f16_ss2(uint32_t d, uint64_t a, uint64_t b, uint32_t id, uint32_t en) {
    asm volatile("{\n\t.reg .pred p;\n\tsetp.ne.u32 p, %5, 0;\n\t"
        "tcgen05.mma.cta_group::2.kind::f16 [%0], %1, %2, %3, {%4,%4,%4,%4,%4,%4,%4,%4}, p;\n\t}"
        :: "r"(d), "l"(a), "l"(b), "r"(id), "r"(0u), "r"(en) : "memory");
}

#define LDTM32(r, addr) \
    asm volatile("tcgen05.ld.sync.aligned.32x32b.x32.b32 " \
        "{%0,%1,%2,%3,%4,%5,%6,%7,%8,%9,%10,%11,%12,%13,%14,%15," \
        "%16,%17,%18,%19,%20,%21,%22,%23,%24,%25,%26,%27,%28,%29,%30,%31}, [%32];" \
        : "=r"((r)[0]),"=r"((r)[1]),"=r"((r)[2]),"=r"((r)[3]),"=r"((r)[4]),"=r"((r)[5]),"=r"((r)[6]),"=r"((r)[7]), \
          "=r"((r)[8]),"=r"((r)[9]),"=r"((r)[10]),"=r"((r)[11]),"=r"((r)[12]),"=r"((r)[13]),"=r"((r)[14]),"=r"((r)[15]), \
          "=r"((r)[16]),"=r"((r)[17]),"=r"((r)[18]),"=r"((r)[19]),"=r"((r)[20]),"=r"((r)[21]),"=r"((r)[22]),"=r"((r)[23]), \
          "=r"((r)[24]),"=r"((r)[25]),"=r"((r)[26]),"=r"((r)[27]),"=r"((r)[28]),"=r"((r)[29]),"=r"((r)[30]),"=r"((r)[31]) \
        : "r"(addr))
#endif  // VQ_TCGEN05

// ================= prep kernel: pack codebook + code norms + zero sse =================
__global__ void vq_prep_c(const float* __restrict__ cb) {
    int gid = blockIdx.x * blockDim.x + threadIdx.x;
    if (gid == 0) g_sse = 0.0;
    if (gid >= K * 32) return;
    int code = gid >> 5, c = gid & 31, k = c * 8;
    float v[8];
    {
        const float4* p = (const float4*)(cb + (size_t)code * D + k);
        float4 a = p[0], b = p[1];
        v[0]=a.x; v[1]=a.y; v[2]=a.z; v[3]=a.w; v[4]=b.x; v[5]=b.y; v[6]=b.z; v[7]=b.w;
    }
    uint4 H, L; float ss = 0.f;
    split_pack8(v, H, L, ss);
    #pragma unroll
    for (int o = 16; o; o >>= 1) ss += __shfl_xor_sync(0xffffffffu, ss, o);
    if ((gid & 31) == 0) g_cbnorm[code] = ss;
    int ct = code >> 7, lc = code & 127;
    int half = lc >> 6, lrow = lc & 63;
    int tb = lrow * 128 + (k & 63) * 2;
    int sw = tb ^ ((tb >> 3) & 0x70);
    size_t base = (size_t)(((ct * NCH + (k >> 6)) * 2) + half) * 16384;
    *(uint4*)(g_cb + base + sw) = H;
    *(uint4*)(g_cb + base + 8192 + sw) = L;
}

// ================= main kernel =================
__global__ __launch_bounds__(NTHREADS, 1) __cluster_dims__(2, 1, 1)
void vq_main(const float* __restrict__ x, const float* __restrict__ cb,
             float* __restrict__ outq, float* __restrict__ outidx)
{
    extern __shared__ char smem[];
    const int tid = threadIdx.x;
    const int wid = tid >> 5;
    const int lane = tid & 31;
    const int blk = blockIdx.x;
    const int row0 = blk * BM;
    int* sel = (int*)(smem + SM_SEL);

#if VQ_TCGEN05
    const uint32_t sb = smem_u32(smem);
    const uint32_t rank = ctarank();
    float* cbns = (float*)(smem + SM_CBN);
    float* rowa = (float*)(smem + SM_ROWA);

    if (tid == 0) {
        #pragma unroll
        for (int s = 0; s < NSTAGE; ++s) {
            MBAR_INIT(sb + OFF_FULL(s), 1);
            MBAR_INIT(sb + OFF_EMPTY(s), 1);
            MBAR_INIT(sb + OFF_FULLX(s), 2);
        }
        #pragma unroll
        for (int p = 0; p < 4; ++p) { MBAR_INIT(sb + OFF_DREADY(p), 1); MBAR_INIT(sb + OFF_EFREE(p), 16); }
    }
    if (wid == 8) { TC_ALLOC2(sb + OFF_TPTR, 512); TC_RELINQ2(); }

    // ---- in-kernel A pack: x rows -> bf16 hi/lo SW128 image + row norms ----
    for (int it = 0; it < 11; ++it) {
        int i = tid + it * NTHREADS;
        if (i < BM * 32) {
            int r = i >> 5, c = i & 31, k = c * 8;
            float v[8];
            {
                const float4* p = (const float4*)(x + (size_t)(row0 + r) * D + k);
                float4 a = p[0], b = p[1];
                v[0]=a.x; v[1]=a.y; v[2]=a.z; v[3]=a.w; v[4]=b.x; v[5]=b.y; v[6]=b.z; v[7]=b.w;
            }
            uint4 H, L; float ss = 0.f;
            split_pack8(v, H, L, ss);
            int tb = ((r >> 3) + (c >> 3) * 16) * 1024 + (r & 7) * 128 + (c & 7) * 16;
            int sw = tb ^ ((tb >> 3) & 0x70);
            *(uint4*)(smem + SM_A + sw) = H;
            *(uint4*)(smem + SM_A + 65536 + sw) = L;
            #pragma unroll
            for (int o = 16; o; o >>= 1) ss += __shfl_xor_sync(0xffffffffu, ss, o);
            if (lane == 0) rowa[r] = ss;
        }
    }
    // ---- preload all codebook norms into smem ----
    for (int i = tid; i < K; i += NTHREADS) cbns[i] = g_cbnorm[i];
    FENCE_ASYNC();
    __syncthreads();
    uint32_t tmem_base;
    asm volatile("ld.shared.b32 %0, [%1];" : "=r"(tmem_base) : "r"(sb + OFF_TPTR));
    CLUSTER_SYNC();   // mbarriers init'd + A tiles visible cluster-wide

    if (wid == 8) {
        // ---------------- MMA warp (leader only issues) ----------------
        if (rank == 0 && elect_one()) {
            const uint64_t adh = MK_DESC(sb + SM_A);
            const uint64_t adl = MK_DESC(sb + SM_A + 65536);
            int i = 0;
            for (int t = 0; t < NCT; ++t) {
                const int p = t & 3;
                MBAR_WAIT(sb + OFF_EFREE(p), 1 ^ ((t >> 2) & 1));
                const uint32_t dbuf = tmem_base + p * 128;
                for (int c = 0; c < NCH; ++c) {
                    const int s = i & (NSTAGE - 1);
                    MBAR_WAIT(sb + OFF_FULLX(s), (i >> 2) & 1);
                    const uint64_t bch = MK_DESC(sb + SM_B + s * 16384);
                    const uint64_t bcl = bch + 512;            // +8KB
                    const uint64_t ah = adh + c * 1024;
                    const uint64_t al = adl + c * 1024;
                    #pragma unroll
                    for (int ks = 0; ks < 4; ++ks)
                        mma_f16_ss2(dbuf, ah + 2 * ks, bch + 2 * ks, IDESC2, !(c == 0 && ks == 0));
                    #pragma unroll
                    for (int ks = 0; ks < 4; ++ks)
                        mma_f16_ss2(dbuf, al + 2 * ks, bch + 2 * ks, IDESC2, 1u);
                    #pragma unroll
                    for (int ks = 0; ks < 4; ++ks)
                        mma_f16_ss2(dbuf, ah + 2 * ks, bcl + 2 * ks, IDESC2, 1u);
                    TC_COMMIT_MC(sb + OFF_EMPTY(s));
                    ++i;
                }
                TC_COMMIT_MC(sb + OFF_DREADY(p));
            }
        }
    } else if (wid == 9) {
        // ---------------- producer warp (each CTA loads its N/2 half) ----------------
        if (elect_one()) {
            for (int i = 0; i < NCT * NCH; ++i) {
                const int s = i & (NSTAGE - 1);
                MBAR_WAIT(sb + OFF_EMPTY(s), 1 ^ ((i >> 2) & 1));
                MBAR_EXPECT(sb + OFF_FULL(s), 16384);
                BULK_CP(sb + SM_B + s * 16384,
                        (const void*)(g_cb + (size_t)(2 * i + rank) * 16384),
                        16384, sb + OFF_FULL(s));
            }
        }
    } else if (wid == 10) {
        // ---------------- relay warp: local FULL -> leader's FULLX ----------------
        if (elect_one()) {
            for (int i = 0; i < NCT * NCH; ++i) {
                const int s = i & (NSTAGE - 1);
                MBAR_WAIT(sb + OFF_FULL(s), (i >> 2) & 1);
                if (rank == 0) { MBAR_ARRIVE(sb + OFF_FULLX(s)); }
                else           { MBAR_ARRIVE_RANK0(sb + OFF_FULLX(s)); }
            }
        }
    } else if (wid < 8) {
        // ------------- epilogue warps: 8 warps, thread owns (row, 64-col half) -------------
        const int row = (wid & 3) * 32 + lane;
        const int colbase = (wid >> 2) * 64;
        const float ra = rowa[row];
        float best = 3.4e38f; int bi = 0;
        for (int t = 0; t < NCT; ++t) {
            const int p = t & 3;
            MBAR_WAIT(sb + OFF_DREADY(p), (t >> 2) & 1);
            TC_FENCE_AFTER();
            const uint32_t dbuf = tmem_base + p * 128 + colbase;
            uint32_t v0[32], v1[32];
            LDTM32(v0, dbuf);
            LDTM32(v1, dbuf + 32);
            TC_WAIT_LD();
            if (lane == 0) {
                if (rank == 0) { MBAR_ARRIVE(sb + OFF_EFREE(p)); }
                else           { MBAR_ARRIVE_RANK0(sb + OFF_EFREE(p)); }
            }
            const int base = t * 128 + colbase;
            #pragma unroll
            for (int j = 0; j < 32; ++j) {
                float tt = __fadd_rn(ra, cbns[base + j]);
                float dd = __fmaf_rn(__uint_as_float(v0[j]), -2.0f, tt);
                if (dd < best) { best = dd; bi = base + j; }
            }
            #pragma unroll
            for (int j = 0; j < 32; ++j) {
                float tt = __fadd_rn(ra, cbns[base + 32 + j]);
                float dd = __fmaf_rn(__uint_as_float(v1[j]), -2.0f, tt);
                if (dd < best) { best = dd; bi = base + 32 + j; }
            }
        }
        // stash partials (combined below)
        __syncthreads();
        float* rv = (float*)(smem + SM_B);
        int*   ri = (int*)(smem + SM_B + 1024);
        rv[tid] = best; ri[tid] = bi;
        __syncthreads();
        if (tid < BM) {
            float va = rv[tid]; int ba = ri[tid];
            float vb = rv[tid + 128]; int bb = ri[tid + 128];
            if (vb < va || (vb == va && bb < ba)) { va = vb; ba = bb; }
            sel[tid] = ba;
            if (outidx) outidx[row0 + tid] = (float)ba;
        }
        goto joined;
    }
    __syncthreads();   // non-epilogue warps: match epilogue's first sync
    __syncthreads();   // match second
joined:
    __syncthreads();   // sel visible to all
    CLUSTER_SYNC();    // both CTAs fully done with TMEM/peer SMEM
    if (wid == 8) TC_DEALLOC2(tmem_base, 512);

#else  // ---------------- SIMT fallback (non-arch-specific compile pass) ----------------
    float* xs = (float*)smem;                 // [BM][257]
    if (tid < BM) {
        const float* xr = x + (size_t)(row0 + tid) * D;
        for (int c = 0; c < D; ++c) xs[tid * 257 + c] = xr[c];
    }
    __syncthreads();
    if (tid < BM) {
        const float* xr = xs + tid * 257;
        float ra = 0.f;
        for (int d = 0; d < D; ++d) ra = __fmaf_rn(xr[d], xr[d], ra);
        float best = 3.4e38f; int bi = 0;
        for (int code = 0; code < K; ++code) {
            const float* cr = cb + (size_t)code * D;
            float dot = 0.f;
            for (int d = 0; d < D; ++d) dot = __fmaf_rn(xr[d], cr[d], dot);
            float dist = __fsub_rn(__fadd_rn(ra, g_cbnorm[code]), __fmul_rn(2.0f, dot));
            if (dist < best) { best = dist; bi = code; }
        }
        sel[tid] = bi;
        if (outidx) outidx[row0 + tid] = (float)bi;
    }
    __syncthreads();
#endif

    // ---- gather, straight-through output fl(x + fl(q-x)), accumulate SSE ----
    {
        float sse = 0.f;
        float4* oq = (float4*)outq;
        const float4* cg = (const float4*)cb;
        const float4* xg = (const float4*)x;
        for (int i = tid; i < BM * (D / 4); i += NTHREADS) {
            int r = i >> 6, c = i & 63;
            float4 q  = cg[(size_t)sel[r] * (D / 4) + c];
            float4 xv = xg[(size_t)(row0 + r) * (D / 4) + c];
            float dx = __fsub_rn(q.x, xv.x), dy = __fsub_rn(q.y, xv.y);
            float dz = __fsub_rn(q.z, xv.z), dw = __fsub_rn(q.w, xv.w);
            float4 o;
            o.x = __fadd_rn(xv.x, dx); o.y = __fadd_rn(xv.y, dy);
            o.z = __fadd_rn(xv.z, dz); o.w = __fadd_rn(xv.w, dw);
            oq[(size_t)(row0 + r) * (D / 4) + c] = o;
            sse += dx * dx + dy * dy + dz * dz + dw * dw;
        }
        #pragma unroll
        for (int o = 16; o; o >>= 1) sse += __shfl_xor_sync(0xffffffffu, sse, o);
        if ((tid & 31) == 0) atomicAdd(&g_sse, (double)sse);
    }
}

__global__ void vq_fin(float* outloss) {
    *outloss = (float)((g_sse / 8388608.0) * 1.25);
}

extern "C" void kernel_launch(void* const* d_in, const int* in_sizes, int n_in,
                              void* d_out, int out_size) {
    const float* x  = (const float*)d_in[0];
    const float* cb = (const float*)d_in[1];
    if (n_in >= 2 && in_sizes[0] == K * D && in_sizes[1] == BT * D) {
        const float* t = x; x = cb; cb = t;
    }

    const size_t NQ = (size_t)BT * D;
    float* outq    = (float*)d_out;
    float* outidx  = nullptr;
    float* outloss = nullptr;
    if ((size_t)out_size >= NQ + BT) outidx = outq + NQ;
    if ((size_t)out_size >= NQ + BT + 1) outloss = outq + NQ + BT;
    else if ((size_t)out_size == NQ + 1) outloss = outq + NQ;

    cudaFuncSetAttribute(vq_main, cudaFuncAttributeMaxDynamicSharedMemorySize, SM_TOT);

    vq_prep_c<<<(K * 32) / 256, 256>>>(cb);
    vq_main<<<BT / BM, NTHREADS, SM_TOT>>>(x, cb, outq, outidx);
    if (outloss) vq_fin<<<1, 1>>>(outloss);
}